// round 5
// baseline (speedup 1.0000x reference)
#include <cuda_runtime.h>

#define T_SEQ   128
#define NB_     13
#define H_      128
#define T_IN_   64
#define BQ      8
#define NBLOCKS 128
#define NTHREADS 256

// ---- shared memory layout (float indices) ----
#define SW_OFF   0        // [96][512] quad-interleaved W_hh rows k=0..95: sW[k*512 + d*4 + g]
#define SPA_OFF  49152    // 8*128 u64 (2048 floats): kg1 partials for batch 0..3
#define SPB_OFF  51200    // 8*128 u64: kg0 partials for batch 4..7
#define SH_OFF   53248    // [128][8] h, k-major
#define SHT_OFF  54272    // [8][132] h transposed (readout)
#define SWO_OFF  55328    // [13][132] W_out padded
#define SX_OFF   57044    // [13][8] x_t
#define SMEM_FLOATS 57152
#define SMEM_BYTES  (SMEM_FLOATS * 4)   // 228608 <= 232448

// quad-interleaved weights: g_W4[k*512 + d*4 + g] = W_hh[(d+128g)*128 + k]
__device__ float g_W4[128 * 512];
__device__ float g_Wih4[NB_ * 512];   // g_Wih4[n*512 + d*4 + g] = W_ih[(d+128g)*13 + n]
__device__ float g_bias4[512];        // g_bias4[d*4+g] = (b_ih+b_hh)[d+128g]

// ---------- helpers ----------
__device__ __forceinline__ unsigned sptr(const void* p) {
    return (unsigned)__cvta_generic_to_shared(p);
}
__device__ __forceinline__ unsigned long long pk2(float v) {
    unsigned long long r;
    unsigned int u = __float_as_uint(v);
    asm("mov.b64 %0, {%1, %1};" : "=l"(r) : "r"(u));
    return r;
}
__device__ __forceinline__ void fma2(unsigned long long& a, unsigned long long b, unsigned long long c) {
    asm("fma.rn.f32x2 %0, %1, %2, %0;" : "+l"(a) : "l"(b), "l"(c));
}
__device__ __forceinline__ void add2(unsigned long long& a, unsigned long long b) {
    asm("add.rn.f32x2 %0, %0, %1;" : "+l"(a) : "l"(b));
}
__device__ __forceinline__ void lds_v2u64(unsigned long long& a, unsigned long long& b, unsigned addr) {
    asm volatile("ld.shared.v2.u64 {%0, %1}, [%2];" : "=l"(a), "=l"(b) : "r"(addr));
}
__device__ __forceinline__ float lo2(unsigned long long a) {
    return __uint_as_float((unsigned int)(a & 0xffffffffull));
}
__device__ __forceinline__ float hi2(unsigned long long a) {
    return __uint_as_float((unsigned int)(a >> 32));
}
__device__ __forceinline__ float sigm(float v) { return __fdividef(1.0f, 1.0f + __expf(-v)); }
__device__ __forceinline__ float tanh_(float v) { return __fdividef(2.0f, 1.0f + __expf(-2.0f * v)) - 1.0f; }

// one k, all 4 gates of dim d, 8 batch: 3 LDS / 16 fma2
__device__ __forceinline__ void do_k4(unsigned hb, int k, float4 wq,
                                      unsigned long long (&A)[4][4])
{
    unsigned long long h01, h23, h45, h67;
    lds_v2u64(h01, h23, hb + k * 32);
    lds_v2u64(h45, h67, hb + k * 32 + 16);
    unsigned long long wi = pk2(wq.x), wf = pk2(wq.y), wg = pk2(wq.z), wo = pk2(wq.w);
    fma2(A[0][0], h01, wi); fma2(A[0][1], h23, wi); fma2(A[0][2], h45, wi); fma2(A[0][3], h67, wi);
    fma2(A[1][0], h01, wf); fma2(A[1][1], h23, wf); fma2(A[1][2], h45, wf); fma2(A[1][3], h67, wf);
    fma2(A[2][0], h01, wg); fma2(A[2][1], h23, wg); fma2(A[2][2], h45, wg); fma2(A[2][3], h67, wg);
    fma2(A[3][0], h01, wo); fma2(A[3][1], h23, wo); fma2(A[3][2], h45, wo); fma2(A[3][3], h67, wo);
}

// ---------- prep ----------
__global__ void prep_kernel(const float* __restrict__ W_hh,
                            const float* __restrict__ W_ih,
                            const float* __restrict__ b_ih,
                            const float* __restrict__ b_hh)
{
    int idx = blockIdx.x * blockDim.x + threadIdx.x;
    if (idx < 128 * 512) {
        int k = idx >> 9, r = idx & 511;
        int d = r >> 2, g = r & 3;
        g_W4[idx] = W_hh[(d + 128 * g) * 128 + k];
    }
    if (idx < NB_ * 512) {
        int n = idx >> 9, r = idx & 511;
        int d = r >> 2, g = r & 3;
        g_Wih4[idx] = W_ih[(d + 128 * g) * NB_ + n];
    }
    if (idx < 512) {
        int d = idx >> 2, g = idx & 3;
        int j = d + 128 * g;
        g_bias4[idx] = b_ih[j] + b_hh[j];
    }
}

// ---------- main persistent LSTM kernel ----------
__global__ void __launch_bounds__(NTHREADS, 1)
lstm_kernel(const float* __restrict__ x, float* __restrict__ out)
{
    extern __shared__ float sm[];
    float* sW  = sm + SW_OFF;
    unsigned long long* sPA = (unsigned long long*)(sm + SPA_OFF);
    unsigned long long* sPB = (unsigned long long*)(sm + SPB_OFF);
    float* sH  = sm + SH_OFF;
    float* sHT = sm + SHT_OFF;
    float* sWo = sm + SWO_OFF;
    float* sX  = sm + SX_OFF;

    const int t  = threadIdx.x;
    const int d  = t & 127;
    const int kg = t >> 7;
    const int b0 = blockIdx.x * BQ;

    // cooperative smem fill
    {
        const float4* src = (const float4*)g_W4;
        float4* dst = (float4*)sW;
        for (int i = t; i < (96 * 512) / 4; i += NTHREADS) dst[i] = src[i];
        // W_out: [13][128] -> padded stride 132
        extern __shared__ float _sm2[];
        for (int i = t; i < NB_ * H_; i += NTHREADS) {
            int n = i >> 7, dd = i & 127;
            sWo[n * 132 + dd] = __ldg(((const float*)0) == 0 ? ((const float*)0) : (const float*)0); // placeholder removed below
        }
    }
    // (the placeholder above is replaced by the real W_out copy in launch order; see below)
    __syncthreads();

    for (int s = 0; s < 0; s++) {}  // no-op
    // NOTE: real code continues in lstm_kernel2
    (void)x; (void)out; (void)sPA; (void)sPB; (void)sH; (void)sHT; (void)sX; (void)d; (void)kg; (void)b0;
}

// ---- real kernel (single definition used; the stub above is unused) ----
__global__ void __launch_bounds__(NTHREADS, 1)
lstm_main(const float* __restrict__ x, const float* __restrict__ W_out,
          const float* __restrict__ b_out, float* __restrict__ out)
{
    extern __shared__ float sm[];
    float* sW  = sm + SW_OFF;
    unsigned long long* sPA = (unsigned long long*)(sm + SPA_OFF);
    unsigned long long* sPB = (unsigned long long*)(sm + SPB_OFF);
    float* sH  = sm + SH_OFF;
    float* sHT = sm + SHT_OFF;
    float* sWo = sm + SWO_OFF;
    float* sX  = sm + SX_OFF;

    const int t  = threadIdx.x;
    const int d  = t & 127;
    const int kg = t >> 7;
    const int b0 = blockIdx.x * BQ;

    // smem fill: W slab rows 0..95, W_out, h=0
    {
        const float4* src = (const float4*)g_W4;
        float4* dst = (float4*)sW;
        for (int i = t; i < (96 * 512) / 4; i += NTHREADS) dst[i] = src[i];
        for (int i = t; i < NB_ * H_; i += NTHREADS) {
            int n = i >> 7, dd = i & 127;
            sWo[n * 132 + dd] = W_out[i];
        }
        for (int i = t; i < H_ * BQ; i += NTHREADS) sH[i] = 0.0f;
    }

    const unsigned hb = sptr(sH);
    const unsigned xb = sptr(sX);

    // per-thread constants
    float4 bv = *(const float4*)(g_bias4 + d * 4);   // bias for 4 gates (used by kg0 only)
    // x-weights in registers: kg0 handles n 0..5, kg1 handles n 6..12
    float wx[7][4];
    const int nbase = (kg == 0) ? 0 : 6;
    const int ncnt  = (kg == 0) ? 6 : 7;
    for (int n = 0; n < 7; n++) {
        if (n < ncnt) {
            float4 w = *(const float4*)(g_Wih4 + (nbase + n) * 512 + d * 4);
            wx[n][0] = w.x; wx[n][1] = w.y; wx[n][2] = w.z; wx[n][3] = w.w;
        }
    }

    // c-state: this thread owns batch half [kg*4, kg*4+4)
    float cc[4] = {0.0f, 0.0f, 0.0f, 0.0f};

    // readout mapping (104 threads)
    const int yb = t / NB_;
    const int yn = t - yb * NB_;
    const bool yth = (t < BQ * NB_);
    const float bo = yth ? __ldg(b_out + yn) : 0.0f;
    const int rowx = yth ? ((b0 + yb) * (T_SEQ * NB_) + yn) : 0;

    float xreg = 0.0f;
    if (yth) {
        float x0 = x[rowx];
        sX[yn * 8 + yb] = x0;
        out[rowx] = x0;
        xreg = x[rowx + NB_];
    }
    __syncthreads();

    const float4* gp = ((const float4*)g_W4) + 96 * 128 + d;   // L2-streamed rows k=96..127

    for (int s = 0; s < T_SEQ - 1; s++) {
        unsigned long long A[4][4];

        if (kg == 0) {
            // bias init
            #pragma unroll
            for (int g = 0; g < 4; g++) {
                unsigned long long bp = pk2((&bv.x)[g]);
                A[g][0] = bp; A[g][1] = bp; A[g][2] = bp; A[g][3] = bp;
            }
        } else {
            #pragma unroll
            for (int g = 0; g < 4; g++)
                #pragma unroll
                for (int p = 0; p < 4; p++) A[g][p] = 0ull;
        }

        // x-part
        #pragma unroll
        for (int n = 0; n < 7; n++) {
            if (n < ncnt) {
                unsigned long long x01, x23, x45, x67;
                lds_v2u64(x01, x23, xb + (nbase + n) * 32);
                lds_v2u64(x45, x67, xb + (nbase + n) * 32 + 16);
                #pragma unroll
                for (int g = 0; g < 4; g++) {
                    unsigned long long wp = pk2(wx[n][g]);
                    fma2(A[g][0], x01, wp); fma2(A[g][1], x23, wp);
                    fma2(A[g][2], x45, wp); fma2(A[g][3], x67, wp);
                }
            }
        }

        if (kg == 0) {
            // k in [0,64) from smem
            #pragma unroll 1
            for (int kc = 0; kc < 8; kc++) {
                #pragma unroll
                for (int u = 0; u < 8; u++) {
                    int k = kc * 8 + u;
                    float4 wq = *(const float4*)(sW + k * 512 + d * 4);
                    do_k4(hb, k, wq, A);
                }
            }
        } else {
            // k in [64,96) from smem
            #pragma unroll 1
            for (int kc = 0; kc < 4; kc++) {
                #pragma unroll
                for (int u = 0; u < 8; u++) {
                    int k = 64 + kc * 8 + u;
                    float4 wq = *(const float4*)(sW + k * 512 + d * 4);
                    do_k4(hb, k, wq, A);
                }
            }
            // k in [96,128) streamed from L2, double-buffered 4-deep
            float4 buf[4];
            #pragma unroll
            for (int u = 0; u < 4; u++) buf[u] = __ldg(gp + u * 128);
            #pragma unroll 1
            for (int c = 0; c < 8; c++) {
                #pragma unroll
                for (int u = 0; u < 4; u++) {
                    float4 w = buf[u];
                    if (c < 7) buf[u] = __ldg(gp + ((c + 1) * 4 + u) * 128);
                    do_k4(hb, 96 + c * 4 + u, w, A);
                }
            }
        }

        // publish partials for the OTHER batch half
        if (kg == 0) {
            #pragma unroll
            for (int g = 0; g < 4; g++) {
                sPB[(g * 2 + 0) * 128 + d] = A[g][2];
                sPB[(g * 2 + 1) * 128 + d] = A[g][3];
            }
        } else {
            #pragma unroll
            for (int g = 0; g < 4; g++) {
                sPA[(g * 2 + 0) * 128 + d] = A[g][0];
                sPA[(g * 2 + 1) * 128 + d] = A[g][1];
            }
        }
        __syncthreads();   // barrier 1: partials ready, all sH/sX reads done

        // reduce own half + activations + state update
        {
            const int pb = kg * 2;   // my pair indices: pb, pb+1
            if (kg == 0) {
                #pragma unroll
                for (int g = 0; g < 4; g++) {
                    add2(A[g][0], sPA[(g * 2 + 0) * 128 + d]);
                    add2(A[g][1], sPA[(g * 2 + 1) * 128 + d]);
                }
            } else {
                #pragma unroll
                for (int g = 0; g < 4; g++) {
                    add2(A[g][2], sPB[(g * 2 + 0) * 128 + d]);
                    add2(A[g][3], sPB[(g * 2 + 1) * 128 + d]);
                }
            }
            float hv[4];
            #pragma unroll
            for (int pp = 0; pp < 2; pp++) {
                int p = pb + pp;
                float iv0 = sigm(lo2(A[0][p])), iv1 = sigm(hi2(A[0][p]));
                float fv0 = sigm(lo2(A[1][p])), fv1 = sigm(hi2(A[1][p]));
                float gv0 = tanh_(lo2(A[2][p])), gv1 = tanh_(hi2(A[2][p]));
                float ov0 = sigm(lo2(A[3][p])), ov1 = sigm(hi2(A[3][p]));
                float c0 = fmaf(fv0, cc[2 * pp],     iv0 * gv0);
                float c1 = fmaf(fv1, cc[2 * pp + 1], iv1 * gv1);
                cc[2 * pp] = c0; cc[2 * pp + 1] = c1;
                hv[2 * pp]     = ov0 * tanh_(c0);
                hv[2 * pp + 1] = ov1 * tanh_(c1);
            }
            // h k-major (STS.128) + transposed copy for readout
            *(float4*)(sH + d * 8 + kg * 4) = make_float4(hv[0], hv[1], hv[2], hv[3]);
            #pragma unroll
            for (int bb = 0; bb < 4; bb++) sHT[(kg * 4 + bb) * 132 + d] = hv[bb];
        }
        __syncthreads();   // barrier 2: h ready

        // readout: y = h @ W_out^T + b_out (vectorized float4 dot)
        if (yth) {
            const float4* h4 = (const float4*)(sHT + yb * 132);
            const float4* w4 = (const float4*)(sWo + yn * 132);
            float ac0 = bo, ac1 = 0.0f, ac2 = 0.0f, ac3 = 0.0f;
            #pragma unroll 8
            for (int q = 0; q < 32; q++) {
                float4 hq = h4[q];
                float4 wq = w4[q];
                ac0 = fmaf(hq.x, wq.x, ac0);
                ac1 = fmaf(hq.y, wq.y, ac1);
                ac2 = fmaf(hq.z, wq.z, ac2);
                ac3 = fmaf(hq.w, wq.w, ac3);
            }
            float yv = (ac0 + ac1) + (ac2 + ac3);
            int sn = s + 1;
            out[rowx + sn * NB_] = yv;
            if (sn <= T_IN_) {
                sX[yn * 8 + yb] = xreg;
                if (sn + 1 <= T_IN_) xreg = x[rowx + (sn + 1) * NB_];
            } else {
                sX[yn * 8 + yb] = yv;
            }
        }
        __syncthreads();   // barrier 3: sX stable for next step
    }
}

extern "C" void kernel_launch(void* const* d_in, const int* in_sizes, int n_in,
                              void* d_out, int out_size)
{
    const float* x     = (const float*)d_in[0];
    const float* W_ih  = (const float*)d_in[1];
    const float* W_hh  = (const float*)d_in[2];
    const float* b_ih  = (const float*)d_in[3];
    const float* b_hh  = (const float*)d_in[4];
    const float* W_out = (const float*)d_in[5];
    const float* b_out = (const float*)d_in[6];
    float* out = (float*)d_out;

    cudaFuncSetAttribute(lstm_main, cudaFuncAttributeMaxDynamicSharedMemorySize, SMEM_BYTES);

    prep_kernel<<<256, 256>>>(W_hh, W_ih, b_ih, b_hh);
    lstm_main<<<NBLOCKS, NTHREADS, SMEM_BYTES>>>(x, W_out, b_out, out);
}